// round 16
// baseline (speedup 1.0000x reference)
#include <cuda_runtime.h>
#include <cuda_fp16.h>
#include <math.h>
#include <stdint.h>

#define T_TOK 4096
#define DIM   1024
#define NEXP  8
#define HID   2816
#define NSLOT (T_TOK*2)

typedef unsigned long long ull;

// ---------------- device scratch (static, no allocs) ----------------
__device__ __align__(16) __half g_W1h[(size_t)NEXP*HID*DIM];
__device__ __align__(16) __half g_W2h[(size_t)NEXP*HID*DIM];
__device__ __align__(16) __half g_W3h[(size_t)NEXP*DIM*HID];
__device__ __align__(16) __half g_xh[(size_t)T_TOK*DIM];
__device__ __align__(16) __half g_Hh[(size_t)NSLOT*HID];
__device__ int   g_tok[NSLOT];
__device__ float g_wslot[NSLOT];
__device__ int   g_te[NSLOT];
__device__ float g_tw[NSLOT];
__device__ int   g_off[NEXP + 1];
__device__ int   g_cur[NEXP];

// ---------------- helpers ----------------
__device__ __forceinline__ uint32_t s2u(const void* p) {
    uint32_t a;
    asm("{ .reg .u64 t; cvta.to.shared.u64 t, %1; cvt.u32.u64 %0, t; }" : "=r"(a) : "l"(p));
    return a;
}
__device__ __forceinline__ unsigned hpack(float lo_elem, float hi_elem) {
    unsigned r;
    asm("cvt.rn.f16x2.f32 %0, %1, %2;" : "=r"(r) : "f"(hi_elem), "f"(lo_elem));
    return r;
}
__device__ __forceinline__ ull f4toh4(float4 v) {
    unsigned p0 = hpack(v.x, v.y);
    unsigned p1 = hpack(v.z, v.w);
    return (ull)p0 | ((ull)p1 << 32);
}
__device__ __forceinline__ void ldm4(uint32_t& r0, uint32_t& r1, uint32_t& r2, uint32_t& r3, uint32_t a) {
    asm volatile("ldmatrix.sync.aligned.m8n8.x4.shared.b16 {%0,%1,%2,%3}, [%4];"
        : "=r"(r0), "=r"(r1), "=r"(r2), "=r"(r3) : "r"(a));
}
__device__ __forceinline__ void mma16816(float* c, const uint32_t* a, const uint32_t* b) {
    asm volatile("mma.sync.aligned.m16n8k16.row.col.f32.f16.f16.f32 "
        "{%0,%1,%2,%3}, {%4,%5,%6,%7}, {%8,%9}, {%0,%1,%2,%3};"
        : "+f"(c[0]), "+f"(c[1]), "+f"(c[2]), "+f"(c[3])
        : "r"(a[0]), "r"(a[1]), "r"(a[2]), "r"(a[3]), "r"(b[0]), "r"(b[1]));
}
__device__ __forceinline__ void cpa16(uint32_t dst, const void* src) {
    asm volatile("cp.async.cg.shared.global [%0], [%1], 16;" :: "r"(dst), "l"(src) : "memory");
}
#define CP_COMMIT() asm volatile("cp.async.commit_group;" ::: "memory")
#define CP_WAIT1()  asm volatile("cp.async.wait_group 1;" ::: "memory")
#define CP_WAIT2()  asm volatile("cp.async.wait_group 2;" ::: "memory")

// smem geometry (halves): k64 chunks, rows padded to 72 (64 + 8); 72 halves = 36 words ≡ 4 mod 32 -> conflict-free ldmatrix
#define ROWP   72
#define APLN   9216                  // one 128-row x 64-half plane incl pad (128*72)
#define S1_STG (3*APLN)              // A + B1 + B2
#define S2_STG (2*APLN)              // A + B
#define SMEM1  (3*S1_STG*2)          // 165888
#define SMEM2  (4*S2_STG*2)          // 147456

// ---------------- k_prep: weight convert + gate + x convert + zero out ----------------
__global__ void __launch_bounds__(256) k_prep(const float* __restrict__ x,
                                              const float* __restrict__ Wg,
                                              const float4* __restrict__ W1,
                                              const float4* __restrict__ W2,
                                              const float4* __restrict__ W3,
                                              float4* __restrict__ out) {
    int bid = blockIdx.x, tid = threadIdx.x;
    // gating on first 512 blocks (8 warps -> 8 tokens per block)
    if (bid < 512) {
        int t = bid * 8 + (tid >> 5);
        int lane = tid & 31;
        const float4* xr = reinterpret_cast<const float4*>(x + (size_t)t * DIM);
        float s[NEXP];
#pragma unroll
        for (int e = 0; e < NEXP; e++) s[e] = 0.f;
        for (int i = lane; i < DIM / 4; i += 32) {
            float4 xv = xr[i];
#pragma unroll
            for (int e = 0; e < NEXP; e++) {
                float4 wv = reinterpret_cast<const float4*>(Wg + (size_t)e * DIM)[i];
                s[e] += xv.x * wv.x + xv.y * wv.y + xv.z * wv.z + xv.w * wv.w;
            }
            unsigned h01 = hpack(xv.x, xv.y);
            unsigned h23 = hpack(xv.z, xv.w);
            *(uint2*)(g_xh + (size_t)t * DIM + i * 4) = make_uint2(h01, h23);
        }
#pragma unroll
        for (int e = 0; e < NEXP; e++) {
#pragma unroll
            for (int o = 16; o > 0; o >>= 1) s[e] += __shfl_xor_sync(0xffffffffu, s[e], o);
        }
        if (lane == 0) {
            int b0 = 0; float v0 = s[0];
#pragma unroll
            for (int e = 1; e < NEXP; e++) if (s[e] > v0) { v0 = s[e]; b0 = e; }
            int b1 = -1; float v1 = -3.4e38f;
#pragma unroll
            for (int e = 0; e < NEXP; e++) if (e != b0 && s[e] > v1) { v1 = s[e]; b1 = e; }
            g_te[t * 2 + 0] = b0;  g_te[t * 2 + 1] = b1;
            g_tw[t * 2 + 0] = v0;  g_tw[t * 2 + 1] = v1;
        }
    }
    // weight conversion, all blocks grid-stride
    const size_t n1 = (size_t)NEXP * HID * DIM / 4;
    size_t stride = (size_t)gridDim.x * blockDim.x;
    for (size_t i = (size_t)bid * blockDim.x + tid; i < n1; i += stride) {
        *(ull*)(g_W1h + i * 4) = f4toh4(W1[i]);
        *(ull*)(g_W2h + i * 4) = f4toh4(W2[i]);
        *(ull*)(g_W3h + i * 4) = f4toh4(W3[i]);
    }
    // zero output
    const size_t no = (size_t)T_TOK * DIM / 4;
    for (size_t i = (size_t)bid * blockDim.x + tid; i < no; i += stride)
        out[i] = make_float4(0.f, 0.f, 0.f, 0.f);
}

// ---------------- k_count: histogram + scan (replaces zero_cnt + atomics + scan) ----------------
__global__ void k_count() {
    __shared__ int h[NEXP];
    int tid = threadIdx.x;
    if (tid < NEXP) h[tid] = 0;
    __syncthreads();
    for (int i = tid; i < NSLOT; i += blockDim.x) atomicAdd(&h[g_te[i]], 1);
    __syncthreads();
    if (tid == 0) {
        int o = 0;
        for (int e = 0; e < NEXP; e++) { g_off[e] = o; g_cur[e] = o; o += h[e]; }
        g_off[NEXP] = o;
    }
}

__global__ void k_assign() {
    int t = blockIdx.x * blockDim.x + threadIdx.x;
    if (t >= T_TOK) return;
#pragma unroll
    for (int k = 0; k < 2; k++) {
        int e = g_te[t * 2 + k];
        int pos = atomicAdd(&g_cur[e], 1);
        g_tok[pos] = t;
        g_wslot[pos] = g_tw[t * 2 + k];
    }
}

// ---------------- stage issue (k64): 512 threads ----------------
// GEMM1: A + B1 + B2, 6 x 16B per thread
__device__ __forceinline__ void issue1(uint32_t smb, int soff, int tid, const int* s_tok,
        const __half* __restrict__ b1, const __half* __restrict__ b2, int k0) {
    int r = tid >> 2, g0 = tid & 3;
#pragma unroll
    for (int j = 0; j < 2; j++) {
        int g = g0 + j * 4;
        uint32_t d = smb + (uint32_t)(soff + r * ROWP + g * 8) * 2;
        cpa16(d, g_xh + (size_t)s_tok[r] * DIM + k0 + g * 8);
        size_t wo = (size_t)r * DIM + k0 + g * 8;
        cpa16(d + APLN * 2, b1 + wo);
        cpa16(d + 2 * APLN * 2, b2 + wo);
    }
}
// GEMM2: A + B, 4 x 16B per thread
__device__ __forceinline__ void issue2(uint32_t smb, int soff, int tid, const int* s_row,
        const __half* __restrict__ b3, int k0) {
    int r = tid >> 2, g0 = tid & 3;
#pragma unroll
    for (int j = 0; j < 2; j++) {
        int g = g0 + j * 4;
        uint32_t d = smb + (uint32_t)(soff + r * ROWP + g * 8) * 2;
        cpa16(d, g_Hh + (size_t)s_row[r] * HID + k0 + g * 8);
        cpa16(d + APLN * 2, b3 + (size_t)r * HID + k0 + g * 8);
    }
}

// ---------------- GEMM1 compute (one k64 chunk) ----------------
__device__ __forceinline__ void comp1(uint32_t smb, int st, int wid, int lane,
                                      float (&A1)[2][4][4], float (&A2)[2][4][4]) {
    int aoff = st * S1_STG;
    int boff = aoff + APLN;
#pragma unroll
    for (int ks = 0; ks < 4; ks++) {
        uint32_t ah[2][4];
#pragma unroll
        for (int mt = 0; mt < 2; mt++) {
            int row = (wid & 3) * 32 + mt * 16 + (lane & 15);
            int hc = ks * 16 + ((lane & 16) >> 1);
            uint32_t ad = smb + (uint32_t)(aoff + row * ROWP + hc) * 2;
            ldm4(ah[mt][0], ah[mt][1], ah[mt][2], ah[mt][3], ad);
        }
        uint32_t b1[4][2], b2[4][2];
#pragma unroll
        for (int p = 0; p < 2; p++) {
            int nr = (wid >> 2) * 32 + p * 16 + (lane & 7) + ((lane & 16) >> 1);
            int hc = ks * 16 + (lane & 8);
            uint32_t bd = smb + (uint32_t)(boff + nr * ROWP + hc) * 2;
            ldm4(b1[2*p][0], b1[2*p][1], b1[2*p+1][0], b1[2*p+1][1], bd);
            ldm4(b2[2*p][0], b2[2*p][1], b2[2*p+1][0], b2[2*p+1][1], bd + APLN * 2);
        }
#pragma unroll
        for (int mt = 0; mt < 2; mt++)
#pragma unroll
            for (int nt = 0; nt < 4; nt++) {
                mma16816(A1[mt][nt], ah[mt], b1[nt]);
                mma16816(A2[mt][nt], ah[mt], b2[nt]);
            }
    }
}

__global__ void __launch_bounds__(512, 1) k_ffn1() {
    int e = blockIdx.z;
    int rbeg = g_off[e], rend = g_off[e + 1];
    int row0 = rbeg + blockIdx.x * 128;   // x = row tile (B-sharing across consecutive CTAs)
    if (row0 >= rend) return;
    int n0 = blockIdx.y * 128;

    extern __shared__ __align__(16) uint16_t sm16[];
    __shared__ int s_tok[128];
    int tid = threadIdx.x, wid = tid >> 5, lane = tid & 31;
    uint32_t smb = s2u(sm16);

    if (tid < 128) {
        int rr = row0 + tid;
        s_tok[tid] = g_tok[rr < rend ? rr : rbeg];
    }
    __syncthreads();

    const __half* b1 = g_W1h + ((size_t)e * HID + n0) * DIM;
    const __half* b2 = g_W2h + ((size_t)e * HID + n0) * DIM;

    float acc1[2][4][4], acc2[2][4][4];
#pragma unroll
    for (int a = 0; a < 2; a++)
#pragma unroll
        for (int b = 0; b < 4; b++)
#pragma unroll
            for (int c = 0; c < 4; c++) { acc1[a][b][c] = 0.f; acc2[a][b][c] = 0.f; }

    const int NC = DIM / 64;  // 16
    issue1(smb, 0 * S1_STG, tid, s_tok, b1, b2, 0);  CP_COMMIT();
    issue1(smb, 1 * S1_STG, tid, s_tok, b1, b2, 64); CP_COMMIT();

    for (int c = 0; c < NC; c++) {
        CP_WAIT1();
        __syncthreads();
        if (c + 2 < NC) issue1(smb, ((c + 2) % 3) * S1_STG, tid, s_tok, b1, b2, (c + 2) * 64);
        CP_COMMIT();
        comp1(smb, c % 3, wid, lane, acc1, acc2);
    }

    // epilogue: silu(g)*u -> fp16 store
    int wr = wid & 3, wc = wid >> 2;
#pragma unroll
    for (int mt = 0; mt < 2; mt++) {
        int rbse = row0 + wr * 32 + mt * 16 + (lane >> 2);
#pragma unroll
        for (int h2 = 0; h2 < 2; h2++) {
            int row = rbse + h2 * 8;
            if (row >= rend) continue;
            int colb = n0 + wc * 32 + (lane & 3) * 2;
            __half* hh = g_Hh + (size_t)row * HID + colb;
#pragma unroll
            for (int nt = 0; nt < 4; nt++) {
                float g0 = acc1[mt][nt][h2 * 2 + 0], u0 = acc2[mt][nt][h2 * 2 + 0];
                float g1 = acc1[mt][nt][h2 * 2 + 1], u1 = acc2[mt][nt][h2 * 2 + 1];
                float hv0 = g0 * u0 / (1.f + expf(-g0));
                float hv1 = g1 * u1 / (1.f + expf(-g1));
                *(unsigned*)(hh + nt * 8) = hpack(hv0, hv1);
            }
        }
    }
}

// ---------------- GEMM2 compute (one k64 chunk) ----------------
__device__ __forceinline__ void comp2(uint32_t smb, int st, int wid, int lane,
                                      float (&A)[2][4][4]) {
    int aoff = st * S2_STG;
    int boff = aoff + APLN;
#pragma unroll
    for (int ks = 0; ks < 4; ks++) {
        uint32_t ah[2][4];
#pragma unroll
        for (int mt = 0; mt < 2; mt++) {
            int row = (wid & 3) * 32 + mt * 16 + (lane & 15);
            int hc = ks * 16 + ((lane & 16) >> 1);
            uint32_t ad = smb + (uint32_t)(aoff + row * ROWP + hc) * 2;
            ldm4(ah[mt][0], ah[mt][1], ah[mt][2], ah[mt][3], ad);
        }
        uint32_t bb[4][2];
#pragma unroll
        for (int p = 0; p < 2; p++) {
            int nr = (wid >> 2) * 32 + p * 16 + (lane & 7) + ((lane & 16) >> 1);
            int hc = ks * 16 + (lane & 8);
            uint32_t bd = smb + (uint32_t)(boff + nr * ROWP + hc) * 2;
            ldm4(bb[2*p][0], bb[2*p][1], bb[2*p+1][0], bb[2*p+1][1], bd);
        }
#pragma unroll
        for (int mt = 0; mt < 2; mt++)
#pragma unroll
            for (int nt = 0; nt < 4; nt++)
                mma16816(A[mt][nt], ah[mt], bb[nt]);
    }
}

__global__ void __launch_bounds__(512, 1) k_ffn2(float* __restrict__ out) {
    int e = blockIdx.z;
    int rbeg = g_off[e], rend = g_off[e + 1];
    int row0 = rbeg + blockIdx.x * 128;
    if (row0 >= rend) return;
    int n0 = blockIdx.y * 128;

    extern __shared__ __align__(16) uint16_t sm16[];
    __shared__ int s_row[128];
    int tid = threadIdx.x, wid = tid >> 5, lane = tid & 31;
    uint32_t smb = s2u(sm16);

    if (tid < 128) {
        int rr = row0 + tid;
        s_row[tid] = (rr < rend) ? rr : rbeg;
    }
    __syncthreads();

    const __half* b3 = g_W3h + ((size_t)e * DIM + n0) * HID;

    float acc[2][4][4];
#pragma unroll
    for (int a = 0; a < 2; a++)
#pragma unroll
        for (int b = 0; b < 4; b++)
#pragma unroll
            for (int c = 0; c < 4; c++) acc[a][b][c] = 0.f;

    const int NC = HID / 64;  // 44
    issue2(smb, 0 * S2_STG, tid, s_row, b3, 0);   CP_COMMIT();
    issue2(smb, 1 * S2_STG, tid, s_row, b3, 64);  CP_COMMIT();
    issue2(smb, 2 * S2_STG, tid, s_row, b3, 128); CP_COMMIT();

    for (int c = 0; c < NC; c++) {
        CP_WAIT2();
        __syncthreads();
        if (c + 3 < NC) issue2(smb, ((c + 3) & 3) * S2_STG, tid, s_row, b3, (c + 3) * 64);
        CP_COMMIT();
        comp2(smb, c & 3, wid, lane, acc);
    }

    // epilogue: scale by gate weight, atomicAdd (2 contributors -> deterministic)
    int wr = wid & 3, wc = wid >> 2;
#pragma unroll
    for (int mt = 0; mt < 2; mt++) {
        int rbse = row0 + wr * 32 + mt * 16 + (lane >> 2);
#pragma unroll
        for (int h2 = 0; h2 < 2; h2++) {
            int slot = rbse + h2 * 8;
            if (slot >= rend) continue;
            int tk = g_tok[slot];
            float wv = g_wslot[slot];
            float* ob = out + (size_t)tk * DIM + n0 + wc * 32 + (lane & 3) * 2;
#pragma unroll
            for (int nt = 0; nt < 4; nt++) {
                atomicAdd(ob + nt * 8,     acc[mt][nt][h2 * 2 + 0] * wv);
                atomicAdd(ob + nt * 8 + 1, acc[mt][nt][h2 * 2 + 1] * wv);
            }
        }
    }
}

// ---------------- launch ----------------
extern "C" void kernel_launch(void* const* d_in, const int* in_sizes, int n_in,
                              void* d_out, int out_size) {
    const float* x  = (const float*)d_in[0];
    const float* Wg = (const float*)d_in[1];
    const float* W1 = (const float*)d_in[2];
    const float* W2 = (const float*)d_in[3];
    const float* W3 = (const float*)d_in[4];
    float* out = (float*)d_out;

    cudaFuncSetAttribute(k_ffn1, cudaFuncAttributeMaxDynamicSharedMemorySize, SMEM1);
    cudaFuncSetAttribute(k_ffn2, cudaFuncAttributeMaxDynamicSharedMemorySize, SMEM2);

    k_prep<<<2048, 256>>>(x, Wg, (const float4*)W1, (const float4*)W2, (const float4*)W3,
                          (float4*)out);
    k_count<<<1, 256>>>();
    k_assign<<<T_TOK / 256, 256>>>();
    k_ffn1<<<dim3(32, HID / 128, NEXP), 512, SMEM1>>>();
    k_ffn2<<<dim3(32, DIM / 128, NEXP), 512, SMEM2>>>(out);
}